// round 3
// baseline (speedup 1.0000x reference)
#include <cuda_runtime.h>
#include <cuda_bf16.h>

// Problem constants (fixed by the dataset)
#define NNODES 1024
#define NEDGES 65536
#define STATE  1024
#define HID    64
#define POOLC  256              // STATE/4
#define INSZ   (NNODES * POOLC) // 262144
#define NH     1024
#define ACT    2

// -------- scratch (no allocations allowed) --------
__device__ float g_agg[NNODES * HID];   // segment-sum of relu hidden, per node
__device__ float g_cnt[NNODES];         // edge counts per node
__device__ float g_z0[INSZ];            // pooled flattened features
__device__ float g_acc[256];            // GEMV accumulator (pre-b3)
__device__ float g_z3[129];             // z3[0..127] + value at [128]
__device__ int   g_is64;                // 1 if edge_index arrived as int64

// -------- K0: zero scratch + detect edge_index dtype --------
__global__ void k_zero(const int* __restrict__ ei32) {
    int i = blockIdx.x * blockDim.x + threadIdx.x;
    if (i < NNODES * HID) g_agg[i] = 0.f;
    if (i < NNODES)       g_cnt[i] = 0.f;
    if (i < 256)          g_acc[i] = 0.f;
    if (i == 0) {
        // int64 values in [0,1024) viewed as int32 pairs -> every odd word 0.
        int all0 = 1;
        for (int k = 0; k < 64; k++)
            if (ei32[2 * k + 1] != 0) { all0 = 0; break; }
        g_is64 = all0;
    }
}

// -------- K1: EdgeConv hidden aggregation --------
// thread t handles (edge = gid>>6, hidden unit c = gid&63)
__global__ void k_edge(const float* __restrict__ x,
                       const int* __restrict__ ei,
                       const float* __restrict__ W1,
                       const float* __restrict__ b1) {
    __shared__ float sW1[4 * HID];
    __shared__ float sb1[HID];
    int t = threadIdx.x;
    if (t < 4 * HID) sW1[t] = W1[t];
    if (t < HID)     sb1[t] = b1[t];
    __syncthreads();

    int gid = blockIdx.x * blockDim.x + t;
    int e = gid >> 6;
    int c = gid & 63;

    int s, d;
    if (g_is64) {
        const long long* e64 = (const long long*)ei;
        s = (int)e64[e];
        d = (int)e64[NEDGES + e];
    } else {
        s = ei[e];
        d = ei[NEDGES + e];
    }
    s &= (NNODES - 1);   // safety mask: can never trap
    d &= (NNODES - 1);

    float xi0 = x[2 * d], xi1 = x[2 * d + 1];
    float e2 = x[2 * s] - xi0;
    float e3 = x[2 * s + 1] - xi1;

    float h = sb1[c]
            + xi0 * sW1[c]
            + xi1 * sW1[HID + c]
            + e2  * sW1[2 * HID + c]
            + e3  * sW1[3 * HID + c];
    h = fmaxf(h, 0.f);
    atomicAdd(&g_agg[d * HID + c], h);
    if (c == 0) atomicAdd(&g_cnt[d], 1.0f);
}

// -------- K2: mean -> @W2 (columns pooled by 4) -> z0 --------
// 16 blocks x 256 threads; block handles 64 nodes; thread t = pooled col j
__global__ __launch_bounds__(256) void k_pool(const float* __restrict__ W2,
                                              const float* __restrict__ b2) {
    __shared__ float mh[64][HID];
    __shared__ float has[64];
    int t = threadIdx.x;
    int node0 = blockIdx.x * 64;

    for (int i = t; i < 64 * HID; i += 256) {
        int n = i >> 6, k = i & 63;
        float cnt = g_cnt[node0 + n];
        mh[n][k] = g_agg[(node0 + n) * HID + k] / fmaxf(cnt, 1.0f);
    }
    if (t < 64) has[t] = (g_cnt[node0 + t] > 0.f) ? 1.f : 0.f;
    __syncthreads();

    // pooled W2 column for this thread: mean of cols 4t..4t+3
    float w2p[HID];
#pragma unroll
    for (int k = 0; k < HID; k++) {
        float4 v = *(const float4*)&W2[k * STATE + 4 * t];
        w2p[k] = 0.25f * (v.x + v.y + v.z + v.w);
    }
    float4 bb = *(const float4*)&b2[4 * t];
    float b2p = 0.25f * (bb.x + bb.y + bb.z + bb.w);

    for (int n = 0; n < 64; n++) {
        float acc = 0.f;
#pragma unroll
        for (int k = 0; k < HID; k++) acc += mh[n][k] * w2p[k];
        g_z0[(node0 + n) * POOLC + t] = acc + b2p * has[n];
    }
}

// -------- K3: split-K GEMV  z0[262144] @ W3[262144, 256] --------
// 2048 blocks x 256 threads; block handles 128 k-rows; thread t = output col
__global__ __launch_bounds__(256) void k_gemv(const float* __restrict__ W3) {
    __shared__ float sz[128];
    int t = threadIdx.x;
    int k0 = blockIdx.x * 128;
    if (t < 128) sz[t] = g_z0[k0 + t];
    __syncthreads();

    float acc = 0.f;
    const float* wp = W3 + (size_t)k0 * 256 + t;
#pragma unroll 8
    for (int k = 0; k < 128; k++) {
        acc += sz[k] * wp[(size_t)k * 256];
    }
    atomicAdd(&g_acc[t], acc);
}

// -------- K4: trunk finalize (b3/leaky -> W4 -> W5 -> value) --------
__global__ __launch_bounds__(256) void k_trunk(const float* __restrict__ b3,
                                               const float* __restrict__ W4,
                                               const float* __restrict__ b4,
                                               const float* __restrict__ W5,
                                               const float* __restrict__ b5,
                                               const float* __restrict__ Wv,
                                               const float* __restrict__ bv) {
    __shared__ float z1[256];
    __shared__ float z2[256];
    __shared__ float z3s[128];
    int t = threadIdx.x;

    float v = g_acc[t] + b3[t];
    z1[t] = (v > 0.f) ? v : 0.01f * v;
    __syncthreads();

    float acc = b4[t];
#pragma unroll 8
    for (int k = 0; k < 256; k++) acc += z1[k] * W4[k * 256 + t];
    z2[t] = (acc > 0.f) ? acc : 0.01f * acc;
    __syncthreads();

    if (t < 128) {
        float a = b5[t];
#pragma unroll 8
        for (int k = 0; k < 256; k++) a += z2[k] * W5[k * 128 + t];
        a = (a > 0.f) ? a : 0.01f * a;
        z3s[t] = a;
        g_z3[t] = a;
    }
    __syncthreads();

    if (t == 0) {
        float val = bv[0];
#pragma unroll 8
        for (int k = 0; k < 128; k++) val += z3s[k] * Wv[k];
        g_z3[128] = val;
    }
}

// -------- K5: dueling heads  q[n,a] --------
// 128 blocks x 256 threads; warp per head n
__global__ __launch_bounds__(256) void k_q(const float* __restrict__ Wa,
                                           const float* __restrict__ ba,
                                           float* __restrict__ out) {
    __shared__ float z3[129];
    int t = threadIdx.x;
    if (t < 129) z3[t] = g_z3[t];
    __syncthreads();

    int warp = t >> 5, lane = t & 31;
    int n = blockIdx.x * 8 + warp;

    float a0 = 0.f, a1 = 0.f;
#pragma unroll
    for (int f = lane; f < 128; f += 32) {
        float2 w = *(const float2*)&Wa[(size_t)(n * 128 + f) * 2];
        a0 += z3[f] * w.x;
        a1 += z3[f] * w.y;
    }
#pragma unroll
    for (int off = 16; off; off >>= 1) {
        a0 += __shfl_down_sync(0xFFFFFFFFu, a0, off);
        a1 += __shfl_down_sync(0xFFFFFFFFu, a1, off);
    }
    if (lane == 0) {
        float adv0 = a0 + ba[2 * n];
        float adv1 = a1 + ba[2 * n + 1];
        float val = z3[128];
        float m = 0.5f * (adv0 + adv1);
        out[2 * n]     = val + adv0 - m;
        out[2 * n + 1] = val + adv1 - m;
    }
}

extern "C" void kernel_launch(void* const* d_in, const int* in_sizes, int n_in,
                              void* d_out, int out_size) {
    const float* x   = (const float*)d_in[0];
    const int*   ei  = (const int*)d_in[1];
    const float* W1  = (const float*)d_in[2];
    const float* b1  = (const float*)d_in[3];
    const float* W2  = (const float*)d_in[4];
    const float* b2  = (const float*)d_in[5];
    const float* W3  = (const float*)d_in[6];
    const float* b3  = (const float*)d_in[7];
    const float* W4  = (const float*)d_in[8];
    const float* b4  = (const float*)d_in[9];
    const float* W5  = (const float*)d_in[10];
    const float* b5  = (const float*)d_in[11];
    const float* Wv  = (const float*)d_in[12];
    const float* bv  = (const float*)d_in[13];
    const float* Wa  = (const float*)d_in[14];
    const float* ba  = (const float*)d_in[15];
    float* out = (float*)d_out;

    k_zero<<<(NNODES * HID + 255) / 256, 256>>>(ei);
    k_edge<<<(NEDGES * HID) / 256, 256>>>(x, ei, W1, b1);
    k_pool<<<NNODES / 64, 256>>>(W2, b2);
    k_gemv<<<INSZ / 128, 256>>>(W3);
    k_trunk<<<1, 256>>>(b3, W4, b4, W5, b5, Wv, bv);
    k_q<<<NH / 8, 256>>>(Wa, ba, out);
}

// round 5
// speedup vs baseline: 1.5949x; 1.5949x over previous
#include <cuda_runtime.h>
#include <cuda_bf16.h>

// Problem constants (fixed by the dataset)
#define NNODES 1024
#define NEDGES 65536
#define STATE  1024
#define HID    64
#define POOLC  256              // STATE/4
#define INSZ   (NNODES * POOLC) // 262144
#define NH     1024
#define ACT    2

// -------- scratch (no allocations allowed) --------
__device__ float g_agg[NNODES * HID];   // segment-sum of relu hidden, per node
__device__ float g_cnt[NNODES];         // edge counts per node
__device__ float g_z0[INSZ];            // pooled flattened features
__device__ float g_acc[256];            // GEMV accumulator (pre-b3)
__device__ float g_z3[129];             // z3[0..127] + value at [128]
__device__ int   g_is64;                // 1 if edge_index arrived as int64

// -------- K0: zero scratch + detect edge_index dtype --------
__global__ void k_zero(const int* __restrict__ ei32) {
    int i = blockIdx.x * blockDim.x + threadIdx.x;
    if (i < NNODES * HID) g_agg[i] = 0.f;
    if (i < NNODES)       g_cnt[i] = 0.f;
    if (i < 256)          g_acc[i] = 0.f;
    if (i == 0) {
        int all0 = 1;
        for (int k = 0; k < 64; k++)
            if (ei32[2 * k + 1] != 0) { all0 = 0; break; }
        g_is64 = all0;
    }
}

// -------- K1: EdgeConv hidden aggregation (vector atomics) --------
// thread handles (edge e = gid>>4, channel group g = gid&15 -> cols 4g..4g+3)
__global__ __launch_bounds__(256) void k_edge(const float* __restrict__ x,
                                              const int* __restrict__ ei,
                                              const float* __restrict__ W1,
                                              const float* __restrict__ b1) {
    __shared__ float4 sW1[4][16];   // [input dim][channel group]
    __shared__ float4 sb1[16];
    int t = threadIdx.x;
    if (t < 64) ((float4*)sW1)[t] = ((const float4*)W1)[t];
    if (t < 16) sb1[t] = ((const float4*)b1)[t];
    __syncthreads();

    int gid = blockIdx.x * blockDim.x + t;
    int e = gid >> 4;
    int g = gid & 15;

    int s, d;
    if (g_is64) {
        const long long* e64 = (const long long*)ei;
        s = (int)e64[e];
        d = (int)e64[NEDGES + e];
    } else {
        s = ei[e];
        d = ei[NEDGES + e];
    }
    s &= (NNODES - 1);
    d &= (NNODES - 1);

    float xi0 = x[2 * d], xi1 = x[2 * d + 1];
    float dx = x[2 * s] - xi0;
    float dy = x[2 * s + 1] - xi1;

    float4 w0 = sW1[0][g], w1 = sW1[1][g], w2 = sW1[2][g], w3 = sW1[3][g];
    float4 b = sb1[g];
    float4 h;
    h.x = fmaxf(b.x + xi0 * w0.x + xi1 * w1.x + dx * w2.x + dy * w3.x, 0.f);
    h.y = fmaxf(b.y + xi0 * w0.y + xi1 * w1.y + dx * w2.y + dy * w3.y, 0.f);
    h.z = fmaxf(b.z + xi0 * w0.z + xi1 * w1.z + dx * w2.z + dy * w3.z, 0.f);
    h.w = fmaxf(b.w + xi0 * w0.w + xi1 * w1.w + dx * w2.w + dy * w3.w, 0.f);

    atomicAdd((float4*)&g_agg[d * HID + 4 * g], h);
    if (g == 0) atomicAdd(&g_cnt[d], 1.0f);
}

// -------- K2: mean -> @W2 (columns pooled by 4) -> z0 --------
__global__ __launch_bounds__(256) void k_pool(const float* __restrict__ W2,
                                              const float* __restrict__ b2) {
    __shared__ float mh[64][HID];
    __shared__ float has[64];
    int t = threadIdx.x;
    int node0 = blockIdx.x * 64;

    for (int i = t; i < 64 * HID; i += 256) {
        int n = i >> 6, k = i & 63;
        float cnt = g_cnt[node0 + n];
        mh[n][k] = g_agg[(node0 + n) * HID + k] / fmaxf(cnt, 1.0f);
    }
    if (t < 64) has[t] = (g_cnt[node0 + t] > 0.f) ? 1.f : 0.f;
    __syncthreads();

    float w2p[HID];
#pragma unroll
    for (int k = 0; k < HID; k++) {
        float4 v = *(const float4*)&W2[k * STATE + 4 * t];
        w2p[k] = 0.25f * (v.x + v.y + v.z + v.w);
    }
    float4 bb = *(const float4*)&b2[4 * t];
    float b2p = 0.25f * (bb.x + bb.y + bb.z + bb.w);

    for (int n = 0; n < 64; n++) {
        float acc = 0.f;
#pragma unroll
        for (int k = 0; k < HID; k++) acc += mh[n][k] * w2p[k];
        g_z0[(node0 + n) * POOLC + t] = acc + b2p * has[n];
    }
}

// -------- K3: split-K GEMV  z0[262144] @ W3[262144, 256], float4 loads --------
// 1024 blocks x 256 threads; block handles 256 k-rows
// thread (q=t>>6, c=t&63): rows k0+4k+q, cols 4c..4c+3
__global__ __launch_bounds__(256) void k_gemv(const float* __restrict__ W3) {
    __shared__ float sz[256];
    __shared__ float part[4][256];
    int t = threadIdx.x;
    int k0 = blockIdx.x * 256;
    sz[t] = g_z0[k0 + t];
    __syncthreads();

    int q = t >> 6, c = t & 63;
    float4 acc = make_float4(0.f, 0.f, 0.f, 0.f);
    const float* base = W3 + (size_t)(k0 + q) * 256 + 4 * c;
#pragma unroll 8
    for (int k = 0; k < 64; k++) {
        float4 w = __ldcs((const float4*)(base + (size_t)k * 1024)); // row k0+4k+q
        float z = sz[4 * k + q];
        acc.x += z * w.x;
        acc.y += z * w.y;
        acc.z += z * w.z;
        acc.w += z * w.w;
    }
    ((float4*)part[q])[c] = acc;
    __syncthreads();

    float s = part[0][t] + part[1][t] + part[2][t] + part[3][t];
    atomicAdd(&g_acc[t], s);
}

// -------- K4: trunk finalize, 1024 threads for MLP bandwidth --------
__global__ __launch_bounds__(1024) void k_trunk(const float* __restrict__ b3,
                                                const float* __restrict__ W4,
                                                const float* __restrict__ b4,
                                                const float* __restrict__ W5,
                                                const float* __restrict__ b5,
                                                const float* __restrict__ Wv,
                                                const float* __restrict__ bv) {
    __shared__ float z1[256];
    __shared__ float z2[256];
    __shared__ float part[4][256];   // also reused as [8][128]
    __shared__ float z3s[128];
    int t = threadIdx.x;

    if (t < 256) {
        float v = g_acc[t] + b3[t];
        z1[t] = (v > 0.f) ? v : 0.01f * v;
    }
    __syncthreads();

    // z2 = leaky(z1 @ W4 + b4): 4-way split-K
    {
        int q = t >> 8, c = t & 255;
        float a = 0.f;
#pragma unroll 8
        for (int k = 0; k < 64; k++) a += z1[q * 64 + k] * W4[(q * 64 + k) * 256 + c];
        part[q][c] = a;
    }
    __syncthreads();
    if (t < 256) {
        float v = part[0][t] + part[1][t] + part[2][t] + part[3][t] + b4[t];
        z2[t] = (v > 0.f) ? v : 0.01f * v;
    }
    __syncthreads();

    // z3 = leaky(z2 @ W5 + b5): 8-way split-K
    {
        int q = t >> 7, c = t & 127;
        float a = 0.f;
#pragma unroll 8
        for (int k = 0; k < 32; k++) a += z2[q * 32 + k] * W5[(q * 32 + k) * 128 + c];
        ((float*)part)[q * 128 + c] = a;
    }
    __syncthreads();
    if (t < 128) {
        float v = b5[t];
#pragma unroll
        for (int j = 0; j < 8; j++) v += ((float*)part)[j * 128 + t];
        v = (v > 0.f) ? v : 0.01f * v;
        z3s[t] = v;
        g_z3[t] = v;
    }
    __syncthreads();

    if (t < 32) {
        float v = 0.f;
#pragma unroll
        for (int k = t; k < 128; k += 32) v += z3s[k] * Wv[k];
#pragma unroll
        for (int off = 16; off; off >>= 1) v += __shfl_down_sync(0xFFFFFFFFu, v, off);
        if (t == 0) g_z3[128] = v + bv[0];
    }
}

// -------- K5: dueling heads, float4 Wa loads --------
__global__ __launch_bounds__(256) void k_q(const float* __restrict__ Wa,
                                           const float* __restrict__ ba,
                                           float* __restrict__ out) {
    __shared__ float z3[129];
    int t = threadIdx.x;
    if (t < 129) z3[t] = g_z3[t];
    __syncthreads();

    int warp = t >> 5, lane = t & 31;
    int n = blockIdx.x * 8 + warp;

    const float4* w = (const float4*)(Wa + (size_t)n * 256);
    float4 u = w[lane];
    float4 v = w[lane + 32];
    int f = 2 * lane;
    float a0 = z3[f] * u.x + z3[f + 1] * u.z + z3[64 + f] * v.x + z3[65 + f] * v.z;
    float a1 = z3[f] * u.y + z3[f + 1] * u.w + z3[64 + f] * v.y + z3[65 + f] * v.w;
#pragma unroll
    for (int off = 16; off; off >>= 1) {
        a0 += __shfl_down_sync(0xFFFFFFFFu, a0, off);
        a1 += __shfl_down_sync(0xFFFFFFFFu, a1, off);
    }
    if (lane == 0) {
        float adv0 = a0 + ba[2 * n];
        float adv1 = a1 + ba[2 * n + 1];
        float val = z3[128];
        float m = 0.5f * (adv0 + adv1);
        out[2 * n]     = val + adv0 - m;
        out[2 * n + 1] = val + adv1 - m;
    }
}

extern "C" void kernel_launch(void* const* d_in, const int* in_sizes, int n_in,
                              void* d_out, int out_size) {
    const float* x   = (const float*)d_in[0];
    const int*   ei  = (const int*)d_in[1];
    const float* W1  = (const float*)d_in[2];
    const float* b1  = (const float*)d_in[3];
    const float* W2  = (const float*)d_in[4];
    const float* b2  = (const float*)d_in[5];
    const float* W3  = (const float*)d_in[6];
    const float* b3  = (const float*)d_in[7];
    const float* W4  = (const float*)d_in[8];
    const float* b4  = (const float*)d_in[9];
    const float* W5  = (const float*)d_in[10];
    const float* b5  = (const float*)d_in[11];
    const float* Wv  = (const float*)d_in[12];
    const float* bv  = (const float*)d_in[13];
    const float* Wa  = (const float*)d_in[14];
    const float* ba  = (const float*)d_in[15];
    float* out = (float*)d_out;

    k_zero<<<(NNODES * HID + 255) / 256, 256>>>(ei);
    k_edge<<<(NEDGES * 16) / 256, 256>>>(x, ei, W1, b1);
    k_pool<<<NNODES / 64, 256>>>(W2, b2);
    k_gemv<<<INSZ / 256, 256>>>(W3);
    k_trunk<<<1, 1024>>>(b3, W4, b4, W5, b5, Wv, bv);
    k_q<<<NH / 8, 256>>>(Wa, ba, out);
}

// round 6
// speedup vs baseline: 1.6104x; 1.0097x over previous
#include <cuda_runtime.h>
#include <cuda_bf16.h>

// Problem constants (fixed by the dataset)
#define NNODES 1024
#define NEDGES 65536
#define STATE  1024
#define HID    64
#define POOLC  256              // STATE/4
#define INSZ   (NNODES * POOLC) // 262144
#define NH     1024
#define ACT    2

// -------- scratch (no allocations allowed) --------
__device__ float g_agg[NNODES * HID];   // segment-sum of relu hidden, per node
__device__ float g_cnt[NNODES];         // edge counts per node
__device__ float g_z0[INSZ];            // pooled flattened features
__device__ float g_acc[256];            // GEMV accumulator (pre-b3)
__device__ float g_z3[129];             // z3[0..127] + value at [128]
__device__ int   g_is64;                // 1 if edge_index arrived as int64

// -------- K0: zero scratch + detect edge_index dtype --------
__global__ void k_zero(const int* __restrict__ ei32) {
    int i = blockIdx.x * blockDim.x + threadIdx.x;
    if (i < NNODES * HID) g_agg[i] = 0.f;
    if (i < NNODES)       g_cnt[i] = 0.f;
    if (i < 256)          g_acc[i] = 0.f;
    if (i == 0) {
        int all0 = 1;
        for (int k = 0; k < 64; k++)
            if (ei32[2 * k + 1] != 0) { all0 = 0; break; }
        g_is64 = all0;
    }
}

// -------- K1: EdgeConv hidden aggregation (vector atomics) --------
// thread handles (edge e = gid>>4, channel group g = gid&15 -> cols 4g..4g+3)
__global__ __launch_bounds__(256) void k_edge(const float* __restrict__ x,
                                              const int* __restrict__ ei,
                                              const float* __restrict__ W1,
                                              const float* __restrict__ b1) {
    __shared__ float4 sW1[4][16];   // [input dim][channel group]
    __shared__ float4 sb1[16];
    int t = threadIdx.x;
    if (t < 64) ((float4*)sW1)[t] = ((const float4*)W1)[t];
    if (t < 16) sb1[t] = ((const float4*)b1)[t];
    __syncthreads();

    int gid = blockIdx.x * blockDim.x + t;
    int e = gid >> 4;
    int g = gid & 15;

    int s, d;
    if (g_is64) {
        const long long* e64 = (const long long*)ei;
        s = (int)e64[e];
        d = (int)e64[NEDGES + e];
    } else {
        s = ei[e];
        d = ei[NEDGES + e];
    }
    s &= (NNODES - 1);
    d &= (NNODES - 1);

    float xi0 = x[2 * d], xi1 = x[2 * d + 1];
    float dx = x[2 * s] - xi0;
    float dy = x[2 * s + 1] - xi1;

    float4 w0 = sW1[0][g], w1 = sW1[1][g], w2 = sW1[2][g], w3 = sW1[3][g];
    float4 b = sb1[g];
    float4 h;
    h.x = fmaxf(b.x + xi0 * w0.x + xi1 * w1.x + dx * w2.x + dy * w3.x, 0.f);
    h.y = fmaxf(b.y + xi0 * w0.y + xi1 * w1.y + dx * w2.y + dy * w3.y, 0.f);
    h.z = fmaxf(b.z + xi0 * w0.z + xi1 * w1.z + dx * w2.z + dy * w3.z, 0.f);
    h.w = fmaxf(b.w + xi0 * w0.w + xi1 * w1.w + dx * w2.w + dy * w3.w, 0.f);

    atomicAdd((float4*)&g_agg[d * HID + 4 * g], h);
    if (g == 0) atomicAdd(&g_cnt[d], 1.0f);
}

// -------- K2: mean -> @W2 (columns pooled by 4) -> z0 --------
__global__ __launch_bounds__(256) void k_pool(const float* __restrict__ W2,
                                              const float* __restrict__ b2) {
    __shared__ float mh[64][HID];
    __shared__ float has[64];
    int t = threadIdx.x;
    int node0 = blockIdx.x * 64;

    for (int i = t; i < 64 * HID; i += 256) {
        int n = i >> 6, k = i & 63;
        float cnt = g_cnt[node0 + n];
        mh[n][k] = g_agg[(node0 + n) * HID + k] / fmaxf(cnt, 1.0f);
    }
    if (t < 64) has[t] = (g_cnt[node0 + t] > 0.f) ? 1.f : 0.f;
    __syncthreads();

    float w2p[HID];
#pragma unroll
    for (int k = 0; k < HID; k++) {
        float4 v = *(const float4*)&W2[k * STATE + 4 * t];
        w2p[k] = 0.25f * (v.x + v.y + v.z + v.w);
    }
    float4 bb = *(const float4*)&b2[4 * t];
    float b2p = 0.25f * (bb.x + bb.y + bb.z + bb.w);

    for (int n = 0; n < 64; n++) {
        float acc = 0.f;
#pragma unroll
        for (int k = 0; k < HID; k++) acc += mh[n][k] * w2p[k];
        g_z0[(node0 + n) * POOLC + t] = acc + b2p * has[n];
    }
}

// -------- K3: split-K GEMV  z0[262144] @ W3[262144, 256], float4 loads --------
// 1024 blocks x 256 threads; block handles 256 k-rows
// thread (q=t>>6, c=t&63): rows k0+4k+q, cols 4c..4c+3
__global__ __launch_bounds__(256) void k_gemv(const float* __restrict__ W3) {
    __shared__ float sz[256];
    __shared__ float part[4][256];
    int t = threadIdx.x;
    int k0 = blockIdx.x * 256;
    sz[t] = g_z0[k0 + t];
    __syncthreads();

    int q = t >> 6, c = t & 63;
    float4 acc = make_float4(0.f, 0.f, 0.f, 0.f);
    const float* base = W3 + (size_t)(k0 + q) * 256 + 4 * c;
#pragma unroll 8
    for (int k = 0; k < 64; k++) {
        float4 w = __ldcs((const float4*)(base + (size_t)k * 1024)); // row k0+4k+q
        float z = sz[4 * k + q];
        acc.x += z * w.x;
        acc.y += z * w.y;
        acc.z += z * w.z;
        acc.w += z * w.w;
    }
    ((float4*)part[q])[c] = acc;
    __syncthreads();

    float s = part[0][t] + part[1][t] + part[2][t] + part[3][t];
    atomicAdd(&g_acc[t], s);
}

// -------- K4: trunk finalize, 1024 threads for MLP bandwidth --------
__global__ __launch_bounds__(1024) void k_trunk(const float* __restrict__ b3,
                                                const float* __restrict__ W4,
                                                const float* __restrict__ b4,
                                                const float* __restrict__ W5,
                                                const float* __restrict__ b5,
                                                const float* __restrict__ Wv,
                                                const float* __restrict__ bv) {
    __shared__ float z1[256];
    __shared__ float z2[256];
    __shared__ float part[4][256];   // also reused as [8][128]
    __shared__ float z3s[128];
    int t = threadIdx.x;

    if (t < 256) {
        float v = g_acc[t] + b3[t];
        z1[t] = (v > 0.f) ? v : 0.01f * v;
    }
    __syncthreads();

    // z2 = leaky(z1 @ W4 + b4): 4-way split-K
    {
        int q = t >> 8, c = t & 255;
        float a = 0.f;
#pragma unroll 8
        for (int k = 0; k < 64; k++) a += z1[q * 64 + k] * W4[(q * 64 + k) * 256 + c];
        part[q][c] = a;
    }
    __syncthreads();
    if (t < 256) {
        float v = part[0][t] + part[1][t] + part[2][t] + part[3][t] + b4[t];
        z2[t] = (v > 0.f) ? v : 0.01f * v;
    }
    __syncthreads();

    // z3 = leaky(z2 @ W5 + b5): 8-way split-K
    {
        int q = t >> 7, c = t & 127;
        float a = 0.f;
#pragma unroll 8
        for (int k = 0; k < 32; k++) a += z2[q * 32 + k] * W5[(q * 32 + k) * 128 + c];
        ((float*)part)[q * 128 + c] = a;
    }
    __syncthreads();
    if (t < 128) {
        float v = b5[t];
#pragma unroll
        for (int j = 0; j < 8; j++) v += ((float*)part)[j * 128 + t];
        v = (v > 0.f) ? v : 0.01f * v;
        z3s[t] = v;
        g_z3[t] = v;
    }
    __syncthreads();

    if (t < 32) {
        float v = 0.f;
#pragma unroll
        for (int k = t; k < 128; k += 32) v += z3s[k] * Wv[k];
#pragma unroll
        for (int off = 16; off; off >>= 1) v += __shfl_down_sync(0xFFFFFFFFu, v, off);
        if (t == 0) g_z3[128] = v + bv[0];
    }
}

// -------- K5: dueling heads, float4 Wa loads --------
__global__ __launch_bounds__(256) void k_q(const float* __restrict__ Wa,
                                           const float* __restrict__ ba,
                                           float* __restrict__ out) {
    __shared__ float z3[129];
    int t = threadIdx.x;
    if (t < 129) z3[t] = g_z3[t];
    __syncthreads();

    int warp = t >> 5, lane = t & 31;
    int n = blockIdx.x * 8 + warp;

    const float4* w = (const float4*)(Wa + (size_t)n * 256);
    float4 u = w[lane];
    float4 v = w[lane + 32];
    int f = 2 * lane;
    float a0 = z3[f] * u.x + z3[f + 1] * u.z + z3[64 + f] * v.x + z3[65 + f] * v.z;
    float a1 = z3[f] * u.y + z3[f + 1] * u.w + z3[64 + f] * v.y + z3[65 + f] * v.w;
#pragma unroll
    for (int off = 16; off; off >>= 1) {
        a0 += __shfl_down_sync(0xFFFFFFFFu, a0, off);
        a1 += __shfl_down_sync(0xFFFFFFFFu, a1, off);
    }
    if (lane == 0) {
        float adv0 = a0 + ba[2 * n];
        float adv1 = a1 + ba[2 * n + 1];
        float val = z3[128];
        float m = 0.5f * (adv0 + adv1);
        out[2 * n]     = val + adv0 - m;
        out[2 * n + 1] = val + adv1 - m;
    }
}

extern "C" void kernel_launch(void* const* d_in, const int* in_sizes, int n_in,
                              void* d_out, int out_size) {
    const float* x   = (const float*)d_in[0];
    const int*   ei  = (const int*)d_in[1];
    const float* W1  = (const float*)d_in[2];
    const float* b1  = (const float*)d_in[3];
    const float* W2  = (const float*)d_in[4];
    const float* b2  = (const float*)d_in[5];
    const float* W3  = (const float*)d_in[6];
    const float* b3  = (const float*)d_in[7];
    const float* W4  = (const float*)d_in[8];
    const float* b4  = (const float*)d_in[9];
    const float* W5  = (const float*)d_in[10];
    const float* b5  = (const float*)d_in[11];
    const float* Wv  = (const float*)d_in[12];
    const float* bv  = (const float*)d_in[13];
    const float* Wa  = (const float*)d_in[14];
    const float* ba  = (const float*)d_in[15];
    float* out = (float*)d_out;

    k_zero<<<(NNODES * HID + 255) / 256, 256>>>(ei);
    k_edge<<<(NEDGES * 16) / 256, 256>>>(x, ei, W1, b1);
    k_pool<<<NNODES / 64, 256>>>(W2, b2);
    k_gemv<<<INSZ / 256, 256>>>(W3);
    k_trunk<<<1, 1024>>>(b3, W4, b4, W5, b5, Wv, bv);
    k_q<<<NH / 8, 256>>>(Wa, ba, out);
}